// round 15
// baseline (speedup 1.0000x reference)
#include <cuda_runtime.h>
#include <cmath>

// ive(v=49.5, z) = ex2( 49.5*lg2(z) - z/ln2 - lgamma(50.5)/ln2 - 49.5 + lnS(z^2)/ln2 )
// with S(s) = sum_k (s/4)^k / (k! (v+1)_k).
//
// lnS(s)/ln2 on s in [0.25, 9900.25]: degree-14 Chebyshev fit (host-built double,
// passed by value), monomial Horner in t=(s-s0)/h, packed fma.rn.f32x2. Single
// ex2 finish, +64 bias, 2^-64 non-FTZ descale (rel_err 1.896727e-5, frozen).
//
// R14: depth-3 RETEST with the register ceiling lifted. R12's depth-3 regression
// was an allocation artifact: plain __launch_bounds__(256) held ptxas at exactly
// 64 regs (4 CTA/SM boundary) and it spilled the third in-flight float4 instead
// of crossing it (L1% 34->41, alu% 19->23). __launch_bounds__(TPB, 3) raises the
// budget to <=85 regs so the third buffer lives in registers. Validity check:
// regs must come back > 64 and L1% <= 36; otherwise experiment void.
// Fallback on flat/regression: R10/R13 depth-2 freeze (44.3us ncu, reproduced).

#define NP   14
#define TPB  256
#define GRID 2048

struct QTab { float q[NP + 1]; float c64; };

static QTab make_tab_host() {
    const double VD = 49.5, S0 = 4950.25, HH = 4950.0;
    const double LN2 = 0.69314718055994530942;
    const int M = 64;
    double f[M];
    for (int j = 0; j < M; j++) {
        double x = std::cos(M_PI * (j + 0.5) / M);
        double s = S0 + HH * x;
        double T = 1.0, sum = 1.0;
        for (int k = 1; k < 700; k++) {
            T *= s / (4.0 * (double)k * (VD + (double)k));
            sum += T;
            if (k > 40 && T < sum * 1e-19) break;
        }
        f[j] = std::log(sum) / LN2;
    }
    double c[NP + 1];
    for (int k = 0; k <= NP; k++) {
        double acc = 0.0;
        for (int j = 0; j < M; j++) acc += f[j] * std::cos(M_PI * k * (j + 0.5) / M);
        c[k] = 2.0 * acc / M;
    }
    c[0] *= 0.5;
    double a[NP + 1] = {0}, Tp[NP + 1] = {0}, Tc[NP + 1] = {0}, Tn[NP + 1];
    Tp[0] = 1.0; a[0] += c[0];
    Tc[1] = 1.0; a[1] += c[1];
    for (int k = 2; k <= NP; k++) {
        for (int m = 0; m <= NP; m++) {
            double v = -Tp[m];
            if (m > 0) v += 2.0 * Tc[m - 1];
            Tn[m] = v;
        }
        for (int m = 0; m <= k; m++) a[m] += c[k] * Tn[m];
        for (int m = 0; m <= NP; m++) { Tp[m] = Tc[m]; Tc[m] = Tn[m]; }
    }
    QTab t;
    for (int m = 0; m <= NP; m++) t.q[m] = (float)a[m];
    t.c64 = (float)(-(std::lgamma(50.5) / LN2) - 49.5 + 64.0);
    return t;
}
static const QTab H_Q = make_tab_host();   // host static init only

typedef unsigned long long ull;
__device__ __forceinline__ ull pack2(float a, float b) {
    ull r; asm("mov.b64 %0, {%1, %2};" : "=l"(r) : "f"(a), "f"(b)); return r;
}
__device__ __forceinline__ void unpack2(ull v, float& a, float& b) {
    asm("mov.b64 {%0, %1}, %2;" : "=f"(a), "=f"(b) : "l"(v));
}
__device__ __forceinline__ ull fma2(ull a, ull b, ull c) {
    ull d; asm("fma.rn.f32x2 %0, %1, %2, %3;" : "=l"(d) : "l"(a), "l"(b), "l"(c));
    return d;
}
__device__ __forceinline__ ull mul2(ull a, ull b) {
    ull d; asm("mul.rn.f32x2 %0, %1, %2;" : "=l"(d) : "l"(a), "l"(b)); return d;
}
__device__ __forceinline__ ull add2(ull a, ull b) {
    ull d; asm("add.rn.f32x2 %0, %1, %2;" : "=l"(d) : "l"(a), "l"(b)); return d;
}
__device__ __forceinline__ float lg2f(float x) {
    float r; asm("lg2.approx.f32 %0, %1;" : "=f"(r) : "f"(x)); return r;
}
__device__ __forceinline__ float ex2f(float x) {
    float r; asm("ex2.approx.f32 %0, %1;" : "=f"(r) : "f"(x)); return r;
}
__device__ __forceinline__ float mulrn(float a, float b) {   // non-FTZ multiply
    float r; asm("mul.rn.f32 %0, %1, %2;" : "=f"(r) : "f"(a), "f"(b)); return r;
}

// process 4 elements (one float4); named scalars + packed regs only.
__device__ __forceinline__ float4 tile4(float4 a, const ull* qs,
                                        ull HI2, ull HC2, ull NIL2, ull C642) {
    ull Z0 = pack2(a.x, a.y), Z1 = pack2(a.z, a.w);

    float l0 = lg2f(a.x), l1 = lg2f(a.y), l2 = lg2f(a.z), l3 = lg2f(a.w);

    ull T0 = fma2(mul2(Z0, Z0), HI2, HC2);      // t = (z*z - s0)/h
    ull T1 = fma2(mul2(Z1, Z1), HI2, HC2);
    ull E0 = fma2(Z0, NIL2, C642);              // -z/ln2 + c64
    ull E1 = fma2(Z1, NIL2, C642);

    ull R0 = qs[NP], R1 = R0;
#pragma unroll
    for (int m = NP - 1; m >= 0; m--) {
        ull Qm = qs[m];                          // LDS.64 broadcast, pre-packed
        R0 = fma2(R0, T0, Qm);
        R1 = fma2(R1, T1, Qm);
    }
    ull G0 = add2(E0, R0);
    ull G1 = add2(E1, R1);

    float g0, g1, g2, g3;
    unpack2(G0, g0, g1); unpack2(G1, g2, g3);
    const float DS = 5.421010862427522e-20f;     // 2^-64
    return make_float4(mulrn(ex2f(fmaf(49.5f, l0, g0)), DS),
                       mulrn(ex2f(fmaf(49.5f, l1, g1)), DS),
                       mulrn(ex2f(fmaf(49.5f, l2, g2)), DS),
                       mulrn(ex2f(fmaf(49.5f, l3, g3)), DS));
}

__global__ void __launch_bounds__(TPB, 3)
ive_kernel(const float* __restrict__ zin, float* __restrict__ out, int n, QTab tab) {
    __shared__ ull qs[NP + 1];
    if (threadIdx.x <= NP) {
        float v = tab.q[threadIdx.x];
        qs[threadIdx.x] = pack2(v, v);
    }
    __syncthreads();

    const float HIF = 1.0f / 4950.0f;
    const float HCF = -4950.25f / 4950.0f;
    const ull HI2  = pack2(HIF, HIF);
    const ull HC2  = pack2(HCF, HCF);
    const ull NIL2 = pack2(-1.44269504088896341f, -1.44269504088896341f);
    const ull C642 = pack2(tab.c64, tab.c64);

    const int n4      = n >> 2;                       // whole float4 tiles
    const int tid     = blockIdx.x * TPB + threadIdx.x;
    const int nthread = GRID * TPB;
    const float4* in4 = (const float4*)zin;
    float4*       o4  = (float4*)out;

    int i = tid;
    if (i < n4) {
        int i1 = i + nthread;
        int i2 = i1 + nthread;
        if (i2 < n4) {
            // depth-3 software pipeline: three loads in flight during compute
            float4 A = __ldcs(in4 + i);
            float4 B = __ldcs(in4 + i1);
            float4 C = __ldcs(in4 + i2);
            int i3 = i2 + nthread;
            while (i3 < n4) {
                float4 D = __ldcs(in4 + i3);
                __stcs(o4 + i, tile4(A, qs, HI2, HC2, NIL2, C642));
                A = B; B = C; C = D;
                i = i1; i1 = i2; i2 = i3; i3 += nthread;
            }
            __stcs(o4 + i,  tile4(A, qs, HI2, HC2, NIL2, C642));
            __stcs(o4 + i1, tile4(B, qs, HI2, HC2, NIL2, C642));
            __stcs(o4 + i2, tile4(C, qs, HI2, HC2, NIL2, C642));
        } else if (i1 < n4) {
            float4 A = __ldcs(in4 + i);
            float4 B = __ldcs(in4 + i1);
            __stcs(o4 + i,  tile4(A, qs, HI2, HC2, NIL2, C642));
            __stcs(o4 + i1, tile4(B, qs, HI2, HC2, NIL2, C642));
        } else {
            float4 A = __ldcs(in4 + i);
            __stcs(o4 + i, tile4(A, qs, HI2, HC2, NIL2, C642));
        }
    }

    // scalar tail (n not divisible by 4)
    int tailstart = n4 << 2;
    for (int j = tailstart + tid; j < n; j += nthread) {
        float z = zin[j];
        float t = fmaf(z * z, HIF, HCF);
        float rr = tab.q[NP];
        for (int m = NP - 1; m >= 0; m--) rr = fmaf(rr, t, tab.q[m]);
        float g = fmaf(z, -1.44269504088896341f, tab.c64) + rr;
        out[j] = mulrn(ex2f(fmaf(49.5f, lg2f(z), g)), 5.421010862427522e-20f);
    }
}

extern "C" void kernel_launch(void* const* d_in, const int* in_sizes, int n_in,
                              void* d_out, int out_size) {
    const float* z = (const float*)d_in[0];
    float* o = (float*)d_out;
    int n = in_sizes[0];
    if (n <= 0) return;
    ive_kernel<<<GRID, TPB>>>(z, o, n, H_Q);
}

// round 16
// speedup vs baseline: 1.0916x; 1.0916x over previous
#include <cuda_runtime.h>
#include <cmath>

// ive(v=49.5, z) = ex2( 49.5*lg2(z) - z/ln2 - lgamma(50.5)/ln2 - 49.5 + lnS(z^2)/ln2 )
// with S(s) = sum_k (s/4)^k / (k! (v+1)_k).
//
// R16 = R10/R13 record kernel (depth-2 pipeline, 44.3us ncu reproduced) with ONE
// change: GRID 2048 -> 592 (= 148 SMs x 4 resident CTAs) — exactly one
// persistent wave, eliminating ~2.5 wave transitions and the ragged final wave.
// Depth-3 is conclusively worse in both reg regimes (spill: 61us; clean@80regs:
// 46.8us) — warp concurrency beats per-warp depth. Do not revisit.
//
// Math (frozen, rel_err 1.896727e-5): degree-14 Chebyshev fit of lnS/ln2 built
// on host in double, monomial Horner in t=(s-s0)/h via packed fma.rn.f32x2,
// single ex2 finish with +64 bias and 2^-64 non-FTZ descale (denormal-exact).
// All state in named scalars / packed ull regs (scalar arrays spill: R6).

#define NP   14
#define TPB  256
#define GRID 592

struct QTab { float q[NP + 1]; float c64; };

static QTab make_tab_host() {
    const double VD = 49.5, S0 = 4950.25, HH = 4950.0;
    const double LN2 = 0.69314718055994530942;
    const int M = 64;
    double f[M];
    for (int j = 0; j < M; j++) {
        double x = std::cos(M_PI * (j + 0.5) / M);
        double s = S0 + HH * x;
        double T = 1.0, sum = 1.0;
        for (int k = 1; k < 700; k++) {
            T *= s / (4.0 * (double)k * (VD + (double)k));
            sum += T;
            if (k > 40 && T < sum * 1e-19) break;
        }
        f[j] = std::log(sum) / LN2;
    }
    double c[NP + 1];
    for (int k = 0; k <= NP; k++) {
        double acc = 0.0;
        for (int j = 0; j < M; j++) acc += f[j] * std::cos(M_PI * k * (j + 0.5) / M);
        c[k] = 2.0 * acc / M;
    }
    c[0] *= 0.5;
    double a[NP + 1] = {0}, Tp[NP + 1] = {0}, Tc[NP + 1] = {0}, Tn[NP + 1];
    Tp[0] = 1.0; a[0] += c[0];
    Tc[1] = 1.0; a[1] += c[1];
    for (int k = 2; k <= NP; k++) {
        for (int m = 0; m <= NP; m++) {
            double v = -Tp[m];
            if (m > 0) v += 2.0 * Tc[m - 1];
            Tn[m] = v;
        }
        for (int m = 0; m <= k; m++) a[m] += c[k] * Tn[m];
        for (int m = 0; m <= NP; m++) { Tp[m] = Tc[m]; Tc[m] = Tn[m]; }
    }
    QTab t;
    for (int m = 0; m <= NP; m++) t.q[m] = (float)a[m];
    t.c64 = (float)(-(std::lgamma(50.5) / LN2) - 49.5 + 64.0);
    return t;
}
static const QTab H_Q = make_tab_host();   // host static init only

typedef unsigned long long ull;
__device__ __forceinline__ ull pack2(float a, float b) {
    ull r; asm("mov.b64 %0, {%1, %2};" : "=l"(r) : "f"(a), "f"(b)); return r;
}
__device__ __forceinline__ void unpack2(ull v, float& a, float& b) {
    asm("mov.b64 {%0, %1}, %2;" : "=f"(a), "=f"(b) : "l"(v));
}
__device__ __forceinline__ ull fma2(ull a, ull b, ull c) {
    ull d; asm("fma.rn.f32x2 %0, %1, %2, %3;" : "=l"(d) : "l"(a), "l"(b), "l"(c));
    return d;
}
__device__ __forceinline__ ull mul2(ull a, ull b) {
    ull d; asm("mul.rn.f32x2 %0, %1, %2;" : "=l"(d) : "l"(a), "l"(b)); return d;
}
__device__ __forceinline__ ull add2(ull a, ull b) {
    ull d; asm("add.rn.f32x2 %0, %1, %2;" : "=l"(d) : "l"(a), "l"(b)); return d;
}
__device__ __forceinline__ float lg2f(float x) {
    float r; asm("lg2.approx.f32 %0, %1;" : "=f"(r) : "f"(x)); return r;
}
__device__ __forceinline__ float ex2f(float x) {
    float r; asm("ex2.approx.f32 %0, %1;" : "=f"(r) : "f"(x)); return r;
}
__device__ __forceinline__ float mulrn(float a, float b) {   // non-FTZ multiply
    float r; asm("mul.rn.f32 %0, %1, %2;" : "=f"(r) : "f"(a), "f"(b)); return r;
}

// process 4 elements (one float4); named scalars + packed regs only.
__device__ __forceinline__ float4 tile4(float4 a, const ull* qs,
                                        ull HI2, ull HC2, ull NIL2, ull C642) {
    ull Z0 = pack2(a.x, a.y), Z1 = pack2(a.z, a.w);

    float l0 = lg2f(a.x), l1 = lg2f(a.y), l2 = lg2f(a.z), l3 = lg2f(a.w);

    ull T0 = fma2(mul2(Z0, Z0), HI2, HC2);      // t = (z*z - s0)/h
    ull T1 = fma2(mul2(Z1, Z1), HI2, HC2);
    ull E0 = fma2(Z0, NIL2, C642);              // -z/ln2 + c64
    ull E1 = fma2(Z1, NIL2, C642);

    ull R0 = qs[NP], R1 = R0;
#pragma unroll
    for (int m = NP - 1; m >= 0; m--) {
        ull Qm = qs[m];                          // LDS.64 broadcast, pre-packed
        R0 = fma2(R0, T0, Qm);
        R1 = fma2(R1, T1, Qm);
    }
    ull G0 = add2(E0, R0);
    ull G1 = add2(E1, R1);

    float g0, g1, g2, g3;
    unpack2(G0, g0, g1); unpack2(G1, g2, g3);
    const float DS = 5.421010862427522e-20f;     // 2^-64
    return make_float4(mulrn(ex2f(fmaf(49.5f, l0, g0)), DS),
                       mulrn(ex2f(fmaf(49.5f, l1, g1)), DS),
                       mulrn(ex2f(fmaf(49.5f, l2, g2)), DS),
                       mulrn(ex2f(fmaf(49.5f, l3, g3)), DS));
}

__global__ void __launch_bounds__(TPB)
ive_kernel(const float* __restrict__ zin, float* __restrict__ out, int n, QTab tab) {
    __shared__ ull qs[NP + 1];
    if (threadIdx.x <= NP) {
        float v = tab.q[threadIdx.x];
        qs[threadIdx.x] = pack2(v, v);
    }
    __syncthreads();

    const float HIF = 1.0f / 4950.0f;
    const float HCF = -4950.25f / 4950.0f;
    const ull HI2  = pack2(HIF, HIF);
    const ull HC2  = pack2(HCF, HCF);
    const ull NIL2 = pack2(-1.44269504088896341f, -1.44269504088896341f);
    const ull C642 = pack2(tab.c64, tab.c64);

    const int n4      = n >> 2;                       // whole float4 tiles
    const int tid     = blockIdx.x * TPB + threadIdx.x;
    const int nthread = GRID * TPB;
    const float4* in4 = (const float4*)zin;
    float4*       o4  = (float4*)out;

    int i = tid;
    if (i < n4) {
        int i1 = i + nthread;
        if (i1 < n4) {
            // depth-2 software pipeline: two loads in flight during compute
            float4 A = __ldcs(in4 + i);
            float4 B = __ldcs(in4 + i1);
            int i2 = i1 + nthread;
            while (i2 < n4) {
                float4 C = __ldcs(in4 + i2);
                __stcs(o4 + i, tile4(A, qs, HI2, HC2, NIL2, C642));
                A = B; B = C;
                i = i1; i1 = i2; i2 += nthread;
            }
            __stcs(o4 + i,  tile4(A, qs, HI2, HC2, NIL2, C642));
            __stcs(o4 + i1, tile4(B, qs, HI2, HC2, NIL2, C642));
        } else {
            float4 A = __ldcs(in4 + i);
            __stcs(o4 + i, tile4(A, qs, HI2, HC2, NIL2, C642));
        }
    }

    // scalar tail (n not divisible by 4)
    int tailstart = n4 << 2;
    for (int j = tailstart + tid; j < n; j += nthread) {
        float z = zin[j];
        float t = fmaf(z * z, HIF, HCF);
        float rr = tab.q[NP];
        for (int m = NP - 1; m >= 0; m--) rr = fmaf(rr, t, tab.q[m]);
        float g = fmaf(z, -1.44269504088896341f, tab.c64) + rr;
        out[j] = mulrn(ex2f(fmaf(49.5f, lg2f(z), g)), 5.421010862427522e-20f);
    }
}

extern "C" void kernel_launch(void* const* d_in, const int* in_sizes, int n_in,
                              void* d_out, int out_size) {
    const float* z = (const float*)d_in[0];
    float* o = (float*)d_out;
    int n = in_sizes[0];
    if (n <= 0) return;
    ive_kernel<<<GRID, TPB>>>(z, o, n, H_Q);
}